// round 15
// baseline (speedup 1.0000x reference)
#include <cuda_runtime.h>
#include <cuda_fp16.h>

// SpatialTransformer: 3D trilinear warp, dense displacement field.
// vol: [B=2, D=160, H=160, W=160, C=2] f32, trf: [B,D,H,W,3] f32 -> out like vol.
//
// R15 = R9 scheme + batch-split PDL pipeline:
//   K1 build(b=0)
//   K2 main(b=0)  [PSS; gridsync waits K1]
//   K3 build(b=1) [PSS; NO gridsync -> overlaps K2; disjoint E region]
//   K4 main(b=1)  [PSS; gridsync waits K3 (already done); fills K2's tail]
//  - E[b][y][x][z] (z-INNERMOST), 8B entries: x-pair {v[y][x][z], v[y][x+1][z]}
//    both channels fp16 (x-clip baked in). 65.5 MB intermediate.
//  - Main: 2 lanes per voxel (even lane -> z0 plane, odd -> z1), 2x 8B gathers
//    per lane (rows y0, y1); lane-pair z-adjacent entries share a 128B line.
//    4 voxels per lane; planes combined via ONE shfl_xor per voxel.
// Reference semantics preserved exactly:
//   l0c = clip(floor(loc),0,159); l1c = clip(l0c+1,0,159)
//   d1  = l1c - loc (floor weight, UNCLIPPED loc); d0 = 1 - d1

#define DIM   160
#define BD    320                // B * D
#define NVOX  (BD * DIM * DIM)   // 8,192,000
#define TZ    16                 // z-tile in prologue
#define ZSP   163                // smem z-stride in float2 units (160 + 3 pad)

// 65.5 MB scratch: x-pair volume, z-innermost (device global, no runtime alloc)
__device__ uint2 g_E[NVOX];

static __device__ __forceinline__ unsigned pack_h2(float a, float b) {
    __half2 h = __floats2half2_rn(a, b);
    return *reinterpret_cast<unsigned*>(&h);
}
static __device__ __forceinline__ unsigned pack_f2(float2 v) {
    return pack_h2(v.x, v.y);
}
static __device__ __forceinline__ float2 h2f(unsigned u) {
    __half2 h = *reinterpret_cast<__half2*>(&u);
    return __half22float2(h);
}

// ---------------------------------------------------------------------------
// Prologue: build E (z-innermost x-pairs) for one batch item via smem
// transpose. grid = (160 (y), 10 (z-tiles)), block = 256. No grid sync —
// instances are independent of everything that precedes them except stream
// order (which PDL relaxes safely: they touch only their own E region).
// ---------------------------------------------------------------------------
__global__ __launch_bounds__(256)
void build_E_kernel(const float* __restrict__ vol, const int b)
{
    __shared__ float2 sm2[TZ * ZSP];   // 16*163*8 = 20.9 KB

    const int y  = blockIdx.x;              // 0..159
    const int by = b * DIM + y;
    const int z0 = blockIdx.y * TZ;
    const int t  = threadIdx.x;
    const float4* __restrict__ v4 = (const float4*)vol;

    // Load TZ z-planes x 160 x as float4 (2 voxels each), coalesced.
    #pragma unroll
    for (int i = 0; i < (TZ * 80) / 256; i++) {
        const int j  = i * 256 + t;
        const int x4 = j % 80;
        const int zz = j / 80;
        const float4 v = v4[((b * DIM + z0 + zz) * DIM + y) * 80 + x4];
        float2* s = &sm2[zz * ZSP + x4 * 2];
        s[0] = make_float2(v.x, v.y);
        s[1] = make_float2(v.z, v.w);
    }
    __syncthreads();

    // Emit entries; k: zz = k&15, x = k>>4 -> E writes in 128B runs.
    #pragma unroll
    for (int i = 0; i < (TZ * DIM) / 256; i++) {
        const int k  = i * 256 + t;
        const int zz = k & (TZ - 1);
        const int x  = k >> 4;
        const int xp = min(x + 1, DIM - 1);
        const float2* s0 = &sm2[zz * ZSP];
        uint2 e;
        e.x = pack_f2(s0[x]);            // (x  )
        e.y = pack_f2(s0[xp]);           // (x+1)
        g_E[(by * DIM + x) * DIM + (z0 + zz)] = e;
    }
}

// ---------------------------------------------------------------------------
// Main (one batch item): 2 lanes per voxel (lane parity = z-plane), 4 voxels
// per lane, 2 gathers per lane per voxel (rows y0, y1). PDL: trf+weights
// before the grid dependency sync, E gathers after.
// grid = (160 (z), 40 (y/4)), block = 320 (160 x-pairs).
// ---------------------------------------------------------------------------
__global__ __launch_bounds__(2 * DIM)
void st_warp_kernel(const float* __restrict__ trf,
                    float* __restrict__ out,
                    const int b)
{
    const int tid = threadIdx.x;
    const int s   = tid & 1;          // 0 -> z0 plane, 1 -> z1 plane
    const int x   = tid >> 1;         // 0..159
    const int yb  = blockIdx.y << 2;  // base y (0,4,...,156)
    const int z   = blockIdx.x;       // 0..159
    const int zb  = b * DIM + z;
    const float bOff = b ? 4096000.0f : 0.0f;    // b * 160^3 (exact f32)
    const float maxl = (float)(DIM - 1);
    const float fz = (float)z;
    const float fx = (float)x;

    const int voxBase = (zb * DIM + yb) * DIM + x;      // q-stride = DIM

    // ---- phase 1 (independent of E): trf loads + weight/index math ----
    float tz[4], ty[4], tx[4];
    #pragma unroll
    for (int q = 0; q < 4; q++) {
        const float* tp = &trf[(voxBase + q * DIM) * 3];
        tz[q] = tp[0];
        ty[q] = tp[1];
        tx[q] = tp[2];
    }

    float wy0[4], wy1[4], wx0[4], wx1[4], wzs[4];
    int   idx0[4], idx1[4];
    #pragma unroll
    for (int q = 0; q < 4; q++) {
        const float lz = fz + tz[q];
        const float ly = (float)(yb + q) + ty[q];
        const float lx = fx + tx[q];
        const float z0f = fminf(fmaxf(floorf(lz), 0.0f), maxl);
        const float y0f = fminf(fmaxf(floorf(ly), 0.0f), maxl);
        const float x0f = fminf(fmaxf(floorf(lx), 0.0f), maxl);
        const float z1f = fminf(z0f + 1.0f, maxl);
        const float y1f = fminf(y0f + 1.0f, maxl);
        const float x1f = fminf(x0f + 1.0f, maxl);
        wy0[q] = y1f - ly;  wy1[q] = 1.0f - wy0[q];
        wx0[q] = x1f - lx;  wx1[q] = 1.0f - wx0[q];
        const float wz0 = z1f - lz;
        wzs[q] = s ? (1.0f - wz0) : wz0;
        const float zsf = s ? z1f : z0f;
        // exact integer arithmetic in f32: values < 2^23
        const float inner = fmaf(x0f, 160.0f, zsf) + bOff;
        idx0[q] = (int)fmaf(y0f, 25600.0f, inner);
        idx1[q] = (int)fmaf(y1f, 25600.0f, inner);
    }

    // ---- gate: stores of the preceding build kernel must be visible ----
    cudaGridDependencySynchronize();

    // ---- phase 2: 8 independent gathers; lane pairs share lines ~7/8 ----
    uint2 eA[4], eB[4];
    #pragma unroll
    for (int q = 0; q < 4; q++) { eA[q] = g_E[idx0[q]]; eB[q] = g_E[idx1[q]]; }

    #pragma unroll
    for (int q = 0; q < 4; q++) {
        const float w00 = wy0[q] * wx0[q], w01 = wy0[q] * wx1[q];
        const float w10 = wy1[q] * wx0[q], w11 = wy1[q] * wx1[q];
        const float2 c00 = h2f(eA[q].x), c01 = h2f(eA[q].y);   // y0 row: x0, x1
        const float2 c10 = h2f(eB[q].x), c11 = h2f(eB[q].y);   // y1 row: x0, x1
        float p0 = w00 * c00.x, p1 = w00 * c00.y;
        p0 = fmaf(w01, c01.x, p0);  p1 = fmaf(w01, c01.y, p1);
        p0 = fmaf(w10, c10.x, p0);  p1 = fmaf(w10, c10.y, p1);
        p0 = fmaf(w11, c11.x, p0);  p1 = fmaf(w11, c11.y, p1);
        const float r0 = wzs[q] * p0;
        const float r1 = wzs[q] * p1;
        // single-shfl combine: each lane exports the channel the peer stores
        const float send = s ? r0 : r1;
        const float recv = __shfl_xor_sync(0xffffffffu, send, 1);
        // lane s stores channel s -> warp stores are contiguous 128B runs
        out[(voxBase + q * DIM) * 2 + s] = (s ? r1 : r0) + recv;
    }
}

extern "C" void kernel_launch(void* const* d_in, const int* in_sizes, int n_in,
                              void* d_out, int out_size)
{
    const float* vol = (const float*)d_in[0];
    const float* trf = (const float*)d_in[1];
    float* out = (float*)d_out;

    cudaLaunchAttribute pss[1];
    pss[0].id = cudaLaunchAttributeProgrammaticStreamSerialization;
    pss[0].val.programmaticStreamSerializationAllowed = 1;

    // K1: build E for b=0 (plain launch)
    {
        cudaLaunchConfig_t cfg = {};
        cfg.gridDim  = dim3(DIM, DIM / TZ, 1);
        cfg.blockDim = dim3(256, 1, 1);
        cudaLaunchKernelEx(&cfg, build_E_kernel, vol, 0);
    }
    // K2: main for b=0 (PSS; gridsync inside waits for K1)
    {
        cudaLaunchConfig_t cfg = {};
        cfg.gridDim  = dim3(DIM, DIM / 4, 1);
        cfg.blockDim = dim3(2 * DIM, 1, 1);
        cfg.attrs    = pss;
        cfg.numAttrs = 1;
        cudaLaunchKernelEx(&cfg, st_warp_kernel, trf, out, 0);
    }
    // K3: build E for b=1 (PSS; no gridsync inside -> overlaps K2;
    // touches only the disjoint b=1 region of g_E)
    {
        cudaLaunchConfig_t cfg = {};
        cfg.gridDim  = dim3(DIM, DIM / TZ, 1);
        cfg.blockDim = dim3(256, 1, 1);
        cfg.attrs    = pss;
        cfg.numAttrs = 1;
        cudaLaunchKernelEx(&cfg, build_E_kernel, vol, 1);
    }
    // K4: main for b=1 (PSS; gridsync waits for K3; fills K2's drain tail)
    {
        cudaLaunchConfig_t cfg = {};
        cfg.gridDim  = dim3(DIM, DIM / 4, 1);
        cfg.blockDim = dim3(2 * DIM, 1, 1);
        cfg.attrs    = pss;
        cfg.numAttrs = 1;
        cudaLaunchKernelEx(&cfg, st_warp_kernel, trf, out, 1);
    }
}